// round 6
// baseline (speedup 1.0000x reference)
#include <cuda_runtime.h>
#include <cuda_bf16.h>
#include <cuda_pipeline.h>
#include <mma.h>
#include <cstdint>

using namespace nvcuda;

#define NAG  8192
#define OBSD 64
#define HID  128
#define ACTD 16

// Scratch (device globals: no allocations allowed)
__device__ float       g_h  [NAG * HID];   // fp32 encoder output
__device__ signed char g_hq [NAG * HID];   // int8 h: q = round(127*h), row-major
__device__ float       g_msg[NAG * HID];   // neighbor-mean messages

// ---------------------------------------------------------------------------
// K1: h = tanh(obs @ W1 + b1) -> g_h (fp32) + g_hq (int8, scale 127).
// 1024 CTAs x 256 threads; one warp per agent, lane l owns cols 4l..4l+3.
// ---------------------------------------------------------------------------
__global__ void __launch_bounds__(256) k1_encoder(const float* __restrict__ obs,
                                                  const float* __restrict__ W1,
                                                  const float* __restrict__ b1) {
    __shared__ __align__(16) float sW1[OBSD * HID];   // 32 KB
    __shared__ float sObs[8][OBSD];                   // 2 KB
    const int t  = threadIdx.x;
    const int a0 = blockIdx.x * 8;

    #pragma unroll
    for (int i = 0; i < (OBSD * HID) / 256; ++i)
        sW1[i * 256 + t] = W1[i * 256 + t];
    #pragma unroll
    for (int i = 0; i < 2; ++i) {
        int idx = i * 256 + t;               // 512 obs floats
        sObs[idx >> 6][idx & 63] = obs[(size_t)(a0 + (idx >> 6)) * OBSD + (idx & 63)];
    }
    __syncthreads();

    const int w = t >> 5, l = t & 31;
    const int agent = a0 + w;
    float acc0 = 0.f, acc1 = 0.f, acc2 = 0.f, acc3 = 0.f;
    #pragma unroll 8
    for (int k = 0; k < OBSD; ++k) {
        float o = sObs[w][k];
        float4 wv = *reinterpret_cast<const float4*>(&sW1[k * HID + l * 4]);
        acc0 = fmaf(o, wv.x, acc0);
        acc1 = fmaf(o, wv.y, acc1);
        acc2 = fmaf(o, wv.z, acc2);
        acc3 = fmaf(o, wv.w, acc3);
    }
    float4 bb = *reinterpret_cast<const float4*>(&b1[l * 4]);
    float h0 = tanhf(acc0 + bb.x);
    float h1 = tanhf(acc1 + bb.y);
    float h2 = tanhf(acc2 + bb.z);
    float h3 = tanhf(acc3 + bb.w);

    const size_t off = (size_t)agent * HID + l * 4;
    float4 hv; hv.x = h0; hv.y = h1; hv.z = h2; hv.w = h3;
    *reinterpret_cast<float4*>(&g_h[off]) = hv;

    int q0 = __float2int_rn(h0 * 127.f);
    int q1 = __float2int_rn(h1 * 127.f);
    int q2 = __float2int_rn(h2 * 127.f);
    int q3 = __float2int_rn(h3 * 127.f);
    unsigned packed = (unsigned)(q0 & 0xFF) | ((unsigned)(q1 & 0xFF) << 8) |
                      ((unsigned)(q2 & 0xFF) << 16) | ((unsigned)(q3 & 0xFF) << 24);
    *reinterpret_cast<unsigned*>(&g_hq[off]) = packed;
}

// ---------------------------------------------------------------------------
// K2: msg = (adj @ h) / max(deg,1) via int8 IMMA (exact int32 accumulation).
// 128 CTAs; tile M=64 x N=128; K=8192 in 128 chunks of 64.
// cp.async 4-deep ring: {A raw int32 17408B, B s8 9216B}. Converted A s8 x2.
// Per chunk: wait -> convert own A words -> ONE barrier -> issue c+3 -> MMA.
// 8 warps: wm(32M) x wn(64N) x kh(k-half); int partials merged in epilogue.
// ---------------------------------------------------------------------------
#define K2_STAGE   (17408 + 9216)          // 26624
#define K2_RING    (4 * K2_STAGE)          // 106496
#define K2_A8      5120                    // 64 x 80 s8
#define K2_SMEM    (K2_RING + 2 * K2_A8)   // 116736
#define NCH        (NAG / 64)              // 128

__global__ void __launch_bounds__(256, 1) k2_msg(const int* __restrict__ adj) {
    extern __shared__ __align__(16) char sm2[];
    __shared__ int sDeg[64];

    const int t   = threadIdx.x;
    const int wid = t >> 5;
    const int m0  = blockIdx.x * 64;
    if (t < 64) sDeg[t] = 0;

    // A issue/convert mapping: row irow (0..63), 16-int32 group ig (0..3)
    const int irow = t >> 2;
    const int ig   = t & 3;
    const char* gA = reinterpret_cast<const char*>(adj) +
                     (size_t)(m0 + irow) * (NAG * 4) + ig * 64;   // +c*256/chunk
    // B issue mapping: k-row kb (0..63), 32B quarter qb (0..3)
    const int kb = t >> 2;
    const int qb = t & 3;
    const char* gB = reinterpret_cast<const char*>(g_hq) +
                     (size_t)kb * HID + qb * 32;                  // +c*64*128/chunk

    // warp MMA mapping
    const int wm = wid & 1;          // M half (32 rows)
    const int wn = (wid >> 1) & 1;   // N half (64 cols)
    const int kh = wid >> 2;         // k half (ks pair)

    wmma::fragment<wmma::accumulator, 16, 16, 16, int> acc[2][4];
    #pragma unroll
    for (int i = 0; i < 2; ++i)
        #pragma unroll
        for (int j = 0; j < 4; ++j)
            wmma::fill_fragment(acc[i][j], 0);

    auto issue_stage = [&](int c) {
        char* sA = sm2 + (c & 3) * K2_STAGE;
        char* sB = sA + 17408;
        const char* ga = gA + (size_t)c * 256;
        const char* gb = gB + (size_t)c * 64 * HID;
        #pragma unroll
        for (int q = 0; q < 4; ++q)
            __pipeline_memcpy_async(sA + irow * 272 + ig * 64 + q * 16, ga + q * 16, 16);
        #pragma unroll
        for (int q = 0; q < 2; ++q)
            __pipeline_memcpy_async(sB + kb * 144 + qb * 32 + q * 16, gb + q * 16, 16);
    };

    issue_stage(0); __pipeline_commit();
    issue_stage(1); __pipeline_commit();
    issue_stage(2); __pipeline_commit();

    int cnt = 0;
    for (int c = 0; c < NCH; ++c) {
        char* sAraw = sm2 + (c & 3) * K2_STAGE;
        char* sBc   = sAraw + 17408;
        char* sA8   = sm2 + K2_RING + (c & 1) * K2_A8;

        __pipeline_wait_prior(2);      // this thread's stage-c copies done

        // convert own 16 int32 {0,1} -> 16 s8 bytes; count degree
        {
            const int4* src = reinterpret_cast<const int4*>(sAraw + irow * 272 + ig * 64);
            int4 v0 = src[0], v1 = src[1], v2 = src[2], v3 = src[3];
            cnt += v0.x + v0.y + v0.z + v0.w + v1.x + v1.y + v1.z + v1.w +
                   v2.x + v2.y + v2.z + v2.w + v3.x + v3.y + v3.z + v3.w;
            uint4 w;
            w.x = (unsigned)(v0.x | (v0.y << 8) | (v0.z << 16) | (v0.w << 24));
            w.y = (unsigned)(v1.x | (v1.y << 8) | (v1.z << 16) | (v1.w << 24));
            w.z = (unsigned)(v2.x | (v2.y << 8) | (v2.z << 16) | (v2.w << 24));
            w.w = (unsigned)(v3.x | (v3.y << 8) | (v3.z << 16) | (v3.w << 24));
            *reinterpret_cast<uint4*>(sA8 + irow * 80 + ig * 16) = w;
        }
        __syncthreads();               // A-s8 + B visible to all

        if (c + 3 < NCH) issue_stage(c + 3);
        __pipeline_commit();

        // IMMA chunk c: warp tile 32x64, ks in {2kh, 2kh+1}
        const signed char* A = reinterpret_cast<const signed char*>(sA8);
        const signed char* B = reinterpret_cast<const signed char*>(sBc);
        #pragma unroll
        for (int s = 0; s < 2; ++s) {
            const int ks = kh * 2 + s;
            wmma::fragment<wmma::matrix_a, 16, 16, 16, signed char, wmma::row_major> af[2];
            wmma::fragment<wmma::matrix_b, 16, 16, 16, signed char, wmma::row_major> bf[4];
            #pragma unroll
            for (int i = 0; i < 2; ++i)
                wmma::load_matrix_sync(af[i], &A[(wm * 32 + i * 16) * 80 + ks * 16], 80);
            #pragma unroll
            for (int j = 0; j < 4; ++j)
                wmma::load_matrix_sync(bf[j], &B[(ks * 16) * 144 + wn * 64 + j * 16], 144);
            #pragma unroll
            for (int i = 0; i < 2; ++i)
                #pragma unroll
                for (int j = 0; j < 4; ++j)
                    wmma::mma_sync(acc[i][j], af[i], bf[j], acc[i][j]);
        }
    }

    atomicAdd(&sDeg[irow], cnt);
    __syncthreads();                   // all MMA reads of ring done

    // epilogue: two int partial tiles [64][132], merge + scale by 1/(127*deg)
    int* sAcc0 = reinterpret_cast<int*>(sm2);
    int* sAcc1 = reinterpret_cast<int*>(sm2 + 33792);
    int* dstAcc = kh ? sAcc1 : sAcc0;
    #pragma unroll
    for (int i = 0; i < 2; ++i)
        #pragma unroll
        for (int j = 0; j < 4; ++j)
            wmma::store_matrix_sync(&dstAcc[(wm * 32 + i * 16) * 132 + wn * 64 + j * 16],
                                    acc[i][j], 132, wmma::mem_row_major);
    __syncthreads();

    #pragma unroll
    for (int i = 0; i < 32; ++i) {
        int idx = i * 256 + t;                 // 8192 outputs
        int row = idx >> 7, col = idx & 127;
        float s = 1.0f / (127.0f * (float)max(sDeg[row], 1));
        g_msg[(size_t)(m0 + row) * HID + col] =
            (float)(sAcc0[row * 132 + col] + sAcc1[row * 132 + col]) * s;
    }
}

// ---------------------------------------------------------------------------
// K3: hid = tanh([h,msg] @ W2 + b2); logits = hid @ W3 + b3.
// 128 CTAs x 64 agents; W2 fully in smem (128KB). Thread computes 4x8 hid tile.
// ---------------------------------------------------------------------------
#define K3_SMEM (4 * (32768 + 16448 + 2048 + 128 + 16))   // 205,632 B

__global__ void __launch_bounds__(256, 1) k3_actor(float* __restrict__ out,
        const float* __restrict__ W2, const float* __restrict__ b2,
        const float* __restrict__ W3, const float* __restrict__ b3) {
    extern __shared__ __align__(16) float sm[];
    float* sW2 = sm;                   // [256][128]
    float* sC  = sm + 32768;           // [64][257] combined; reused as hid [64][129]
    float* sW3 = sC + 16448;           // [128][16]
    float* sb2 = sW3 + 2048;           // [128]
    float* sb3 = sb2 + 128;            // [16]

    const int t  = threadIdx.x;
    const int a0 = blockIdx.x * 64;

    #pragma unroll 4
    for (int i = 0; i < 128; ++i) sW2[i * 256 + t] = W2[i * 256 + t];
    #pragma unroll
    for (int i = 0; i < 8; ++i)   sW3[i * 256 + t] = W3[i * 256 + t];
    if (t < 128) sb2[t] = b2[t];
    if (t < 16)  sb3[t] = b3[t];
    #pragma unroll 4
    for (int i = 0; i < 32; ++i) {
        int idx = i * 256 + t;             // 8192 (agent,col) pairs
        int a = idx >> 7, k = idx & 127;
        sC[a * 257 + k]       = g_h  [(size_t)(a0 + a) * HID + k];
        sC[a * 257 + 128 + k] = g_msg[(size_t)(a0 + a) * HID + k];
    }
    __syncthreads();

    const int ar = t >> 4;    // agents ar*4 .. ar*4+3
    const int cc = t & 15;    // cols cc*8 .. cc*8+7
    float acc[4][8];
    #pragma unroll
    for (int j = 0; j < 4; ++j)
        #pragma unroll
        for (int i = 0; i < 8; ++i) acc[j][i] = 0.f;

    #pragma unroll 2
    for (int k = 0; k < 2 * HID; ++k) {
        float4 w0 = *reinterpret_cast<const float4*>(&sW2[k * 128 + cc * 8]);
        float4 w1 = *reinterpret_cast<const float4*>(&sW2[k * 128 + cc * 8 + 4]);
        #pragma unroll
        for (int j = 0; j < 4; ++j) {
            float cv = sC[(ar * 4 + j) * 257 + k];
            acc[j][0] = fmaf(cv, w0.x, acc[j][0]);
            acc[j][1] = fmaf(cv, w0.y, acc[j][1]);
            acc[j][2] = fmaf(cv, w0.z, acc[j][2]);
            acc[j][3] = fmaf(cv, w0.w, acc[j][3]);
            acc[j][4] = fmaf(cv, w1.x, acc[j][4]);
            acc[j][5] = fmaf(cv, w1.y, acc[j][5]);
            acc[j][6] = fmaf(cv, w1.z, acc[j][6]);
            acc[j][7] = fmaf(cv, w1.w, acc[j][7]);
        }
    }
    __syncthreads();                      // all comb reads done; reuse sC as hid
    float* sH = sC;                       // [64][129]
    #pragma unroll
    for (int j = 0; j < 4; ++j) {
        int a = ar * 4 + j;
        #pragma unroll
        for (int i = 0; i < 8; ++i) {
            int ccol = cc * 8 + i;
            sH[a * 129 + ccol] = tanhf(acc[j][i] + sb2[ccol]);
        }
    }
    __syncthreads();

    const int a  = t >> 2;   // 0..63
    const int cq = t & 3;    // col quad
    float4 lg; lg.x = 0.f; lg.y = 0.f; lg.z = 0.f; lg.w = 0.f;
    #pragma unroll 8
    for (int k = 0; k < HID; ++k) {
        float hv  = sH[a * 129 + k];
        float4 w3 = *reinterpret_cast<const float4*>(&sW3[k * 16 + cq * 4]);
        lg.x = fmaf(hv, w3.x, lg.x);
        lg.y = fmaf(hv, w3.y, lg.y);
        lg.z = fmaf(hv, w3.z, lg.z);
        lg.w = fmaf(hv, w3.w, lg.w);
    }
    lg.x += sb3[cq * 4 + 0];
    lg.y += sb3[cq * 4 + 1];
    lg.z += sb3[cq * 4 + 2];
    lg.w += sb3[cq * 4 + 3];
    *reinterpret_cast<float4*>(&out[(size_t)(a0 + a) * ACTD + cq * 4]) = lg;
}

// ---------------------------------------------------------------------------
extern "C" void kernel_launch(void* const* d_in, const int* in_sizes, int n_in,
                              void* d_out, int out_size) {
    const float* obs = (const float*)d_in[0];
    const int*   adj = (const int*)  d_in[1];
    const float* W1  = (const float*)d_in[2];
    const float* b1  = (const float*)d_in[3];
    const float* W2  = (const float*)d_in[4];
    const float* b2  = (const float*)d_in[5];
    const float* W3  = (const float*)d_in[6];
    const float* b3  = (const float*)d_in[7];
    float* out = (float*)d_out;

    cudaFuncSetAttribute(k2_msg,   cudaFuncAttributeMaxDynamicSharedMemorySize, K2_SMEM);
    cudaFuncSetAttribute(k3_actor, cudaFuncAttributeMaxDynamicSharedMemorySize, K3_SMEM);

    k1_encoder<<<NAG / 8, 256>>>(obs, W1, b1);
    k2_msg    <<<NAG / 64, 256, K2_SMEM>>>(adj);
    k3_actor  <<<NAG / 64, 256, K3_SMEM>>>(out, W2, b2, W3, b3);
}

// round 7
// speedup vs baseline: 1.5953x; 1.5953x over previous
#include <cuda_runtime.h>
#include <cuda_bf16.h>
#include <cuda_pipeline.h>
#include <cstdint>

#define NAG  8192
#define OBSD 64
#define HID  128
#define ACTD 16
#define KSPL 8                      // K-split factor
#define NCH2 (NAG / 64 / KSPL)      // 16 chunks per K2 CTA

// Scratch (device globals: no allocations allowed)
__device__ float       g_h   [NAG * HID];          // fp32 encoder output
__device__ int         g_q4  [(NAG / 4) * HID];    // packed s8 h: word[kg][col] = q[4kg..4kg+3][col]
__device__ int         g_msgp[KSPL][NAG * HID];    // partial int sums of adj@q
__device__ int         g_degp[KSPL][NAG];          // partial degrees

// ---------------------------------------------------------------------------
// K1: h = tanh(obs @ W1 + b1) -> g_h (fp32) + g_q4 (packed s8, scale 127).
// 1024 CTAs x 256 threads; one warp per agent, lane l owns cols 4l..4l+3.
// ---------------------------------------------------------------------------
__global__ void __launch_bounds__(256) k1_encoder(const float* __restrict__ obs,
                                                  const float* __restrict__ W1,
                                                  const float* __restrict__ b1) {
    __shared__ __align__(16) float sW1[OBSD * HID];   // 32 KB
    __shared__ float sObs[8][OBSD];                   // 2 KB
    __shared__ unsigned char sQ[8][HID];              // 1 KB
    const int t  = threadIdx.x;
    const int a0 = blockIdx.x * 8;

    #pragma unroll
    for (int i = 0; i < (OBSD * HID) / 256; ++i)
        sW1[i * 256 + t] = W1[i * 256 + t];
    #pragma unroll
    for (int i = 0; i < 2; ++i) {
        int idx = i * 256 + t;               // 512 obs floats
        sObs[idx >> 6][idx & 63] = obs[(size_t)(a0 + (idx >> 6)) * OBSD + (idx & 63)];
    }
    __syncthreads();

    const int w = t >> 5, l = t & 31;
    const int agent = a0 + w;
    float acc0 = 0.f, acc1 = 0.f, acc2 = 0.f, acc3 = 0.f;
    #pragma unroll 8
    for (int k = 0; k < OBSD; ++k) {
        float o = sObs[w][k];
        float4 wv = *reinterpret_cast<const float4*>(&sW1[k * HID + l * 4]);
        acc0 = fmaf(o, wv.x, acc0);
        acc1 = fmaf(o, wv.y, acc1);
        acc2 = fmaf(o, wv.z, acc2);
        acc3 = fmaf(o, wv.w, acc3);
    }
    float4 bb = *reinterpret_cast<const float4*>(&b1[l * 4]);
    float h0 = tanhf(acc0 + bb.x);
    float h1 = tanhf(acc1 + bb.y);
    float h2 = tanhf(acc2 + bb.z);
    float h3 = tanhf(acc3 + bb.w);

    const size_t off = (size_t)agent * HID + l * 4;
    float4 hv; hv.x = h0; hv.y = h1; hv.z = h2; hv.w = h3;
    *reinterpret_cast<float4*>(&g_h[off]) = hv;

    sQ[w][l * 4 + 0] = (unsigned char)(__float2int_rn(h0 * 127.f) & 0xFF);
    sQ[w][l * 4 + 1] = (unsigned char)(__float2int_rn(h1 * 127.f) & 0xFF);
    sQ[w][l * 4 + 2] = (unsigned char)(__float2int_rn(h2 * 127.f) & 0xFF);
    sQ[w][l * 4 + 3] = (unsigned char)(__float2int_rn(h3 * 127.f) & 0xFF);
    __syncthreads();

    // pack 4 agents per word: g_q4[(a0/4 + g)][col]
    const int g   = t >> 7;          // 0..1
    const int col = t & 127;
    unsigned wd = (unsigned)sQ[g * 4 + 0][col]
                | ((unsigned)sQ[g * 4 + 1][col] << 8)
                | ((unsigned)sQ[g * 4 + 2][col] << 16)
                | ((unsigned)sQ[g * 4 + 3][col] << 24);
    g_q4[((a0 >> 2) + g) * HID + col] = (int)wd;
}

// ---------------------------------------------------------------------------
// K2: partial[half] = adj[:, khalf] @ q via dp4a (exact int32 accumulation).
// Grid 1024 = 128 M-tiles (64 rows) x 8 K-splits (1024 k's = 16 chunks of 64).
// cp.async 4-deep ring: {A raw int32 64x272B, B packed 16kg x 512B}.
// Per chunk: wait -> convert own A (pack bytes, count deg) -> barrier ->
// issue c+3 -> dp4a. Thread computes 4 rows x 8 cols int accumulators.
// ---------------------------------------------------------------------------
#define K2_AS    17408                     // A raw stage: 64*272
#define K2_BS    8192                      // B stage: 16*512
#define K2_STAGE (K2_AS + K2_BS)           // 25600
#define K2_RING  (4 * K2_STAGE)            // 102400
#define K2_A4    5120                      // packed A: 64 rows * 80 B
#define K2_SMEM  (K2_RING + 2 * K2_A4)     // 112640

__global__ void __launch_bounds__(256, 1) k2_msg(const int* __restrict__ adj) {
    extern __shared__ __align__(16) char sm2[];
    __shared__ int sDeg[64];

    const int t    = threadIdx.x;
    const int mt   = blockIdx.x & 127;
    const int half = blockIdx.x >> 7;       // 0..7
    const int m0   = mt * 64;
    const int k0   = half * (NAG / KSPL);   // 1024
    const int kg0  = half * (NAG / KSPL / 4);
    if (t < 64) sDeg[t] = 0;

    // A copy/convert mapping: row irow (0..63), 16-int32 group ig (0..3)
    const int irow = t >> 2;
    const int ig   = t & 3;
    const int* gA  = adj + (size_t)(m0 + irow) * NAG + k0 + ig * 16;
    // B copy mapping: kg row bkg (0..15), 32B segment bseg (0..15)
    const int bkg  = t >> 4;
    const int bseg = t & 15;
    const int* gB  = g_q4 + (size_t)(kg0 + bkg) * HID + bseg * 8;

    // compute mapping: rows 4*trow.., cols 8*tcol..
    const int trow = t >> 4;
    const int tcol = t & 15;

    int acc[4][8];
    #pragma unroll
    for (int r = 0; r < 4; ++r)
        #pragma unroll
        for (int j = 0; j < 8; ++j) acc[r][j] = 0;

    auto issue_stage = [&](int c) {
        char* sA = sm2 + (c & 3) * K2_STAGE;
        char* sB = sA + K2_AS;
        const int* ga = gA + c * 64;
        const int* gb = gB + c * 16 * HID;
        #pragma unroll
        for (int q = 0; q < 4; ++q)
            __pipeline_memcpy_async(sA + irow * 272 + ig * 64 + q * 16, ga + q * 4, 16);
        #pragma unroll
        for (int q = 0; q < 2; ++q)
            __pipeline_memcpy_async(sB + bkg * 512 + bseg * 32 + q * 16, gb + q * 4, 16);
    };

    issue_stage(0); __pipeline_commit();
    issue_stage(1); __pipeline_commit();
    issue_stage(2); __pipeline_commit();

    int cnt = 0;
    for (int c = 0; c < NCH2; ++c) {
        char* sAraw = sm2 + (c & 3) * K2_STAGE;
        char* sBc   = sAraw + K2_AS;
        int*  sA4   = reinterpret_cast<int*>(sm2 + K2_RING + (c & 1) * K2_A4);

        __pipeline_wait_prior(2);      // this thread's stage-c copies done

        // convert own 16 int32 {0,1} -> 4 packed-byte words; count degree
        {
            const int4* src = reinterpret_cast<const int4*>(sAraw + irow * 272 + ig * 64);
            int4 v0 = src[0], v1 = src[1], v2 = src[2], v3 = src[3];
            cnt += v0.x + v0.y + v0.z + v0.w + v1.x + v1.y + v1.z + v1.w +
                   v2.x + v2.y + v2.z + v2.w + v3.x + v3.y + v3.z + v3.w;
            int4 w;
            w.x = v0.x | (v0.y << 8) | (v0.z << 16) | (v0.w << 24);
            w.y = v1.x | (v1.y << 8) | (v1.z << 16) | (v1.w << 24);
            w.z = v2.x | (v2.y << 8) | (v2.z << 16) | (v2.w << 24);
            w.w = v3.x | (v3.y << 8) | (v3.z << 16) | (v3.w << 24);
            *reinterpret_cast<int4*>(&sA4[irow * 20 + ig * 4]) = w;
        }
        __syncthreads();               // packed A + B visible to all

        if (c + 3 < NCH2) issue_stage(c + 3);
        __pipeline_commit();

        // dp4a over 16 kg of this chunk
        const int* sB4 = reinterpret_cast<const int*>(sBc);
        #pragma unroll 4
        for (int kg = 0; kg < 16; ++kg) {
            int a[4];
            #pragma unroll
            for (int r = 0; r < 4; ++r)
                a[r] = sA4[(4 * trow + r) * 20 + kg];
            int4 b0 = *reinterpret_cast<const int4*>(&sB4[kg * 128 + tcol * 8]);
            int4 b1 = *reinterpret_cast<const int4*>(&sB4[kg * 128 + tcol * 8 + 4]);
            #pragma unroll
            for (int r = 0; r < 4; ++r) {
                acc[r][0] = __dp4a(a[r], b0.x, acc[r][0]);
                acc[r][1] = __dp4a(a[r], b0.y, acc[r][1]);
                acc[r][2] = __dp4a(a[r], b0.z, acc[r][2]);
                acc[r][3] = __dp4a(a[r], b0.w, acc[r][3]);
                acc[r][4] = __dp4a(a[r], b1.x, acc[r][4]);
                acc[r][5] = __dp4a(a[r], b1.y, acc[r][5]);
                acc[r][6] = __dp4a(a[r], b1.z, acc[r][6]);
                acc[r][7] = __dp4a(a[r], b1.w, acc[r][7]);
            }
        }
    }

    atomicAdd(&sDeg[irow], cnt);

    // write int partials straight from registers (coalesced int4 x2 per row)
    int* dst = g_msgp[half];
    #pragma unroll
    for (int r = 0; r < 4; ++r) {
        int* p = dst + (size_t)(m0 + 4 * trow + r) * HID + tcol * 8;
        *reinterpret_cast<int4*>(p)     = make_int4(acc[r][0], acc[r][1], acc[r][2], acc[r][3]);
        *reinterpret_cast<int4*>(p + 4) = make_int4(acc[r][4], acc[r][5], acc[r][6], acc[r][7]);
    }
    __syncthreads();
    if (t < 64) g_degp[half][m0 + t] = sDeg[t];
}

// ---------------------------------------------------------------------------
// K3: merge partials -> msg; hid = tanh([h,msg] @ W2 + b2); out = hid @ W3 + b3.
// 128 CTAs x 64 agents; W2 fully in smem. Thread computes 4x8 hid tile.
// ---------------------------------------------------------------------------
#define K3_SMEM (4 * (32768 + 16448 + 2048 + 128 + 16 + 64))   // 205,888 B

__global__ void __launch_bounds__(256, 1) k3_actor(float* __restrict__ out,
        const float* __restrict__ W2, const float* __restrict__ b2,
        const float* __restrict__ W3, const float* __restrict__ b3) {
    extern __shared__ __align__(16) float sm[];
    float* sW2 = sm;                   // [256][128]
    float* sC  = sm + 32768;           // [64][257] combined; reused as hid [64][129]
    float* sW3 = sC + 16448;           // [128][16]
    float* sb2 = sW3 + 2048;           // [128]
    float* sb3 = sb2 + 128;            // [16]
    float* sInv = sb3 + 16;            // [64] 1/(127*deg)

    const int t  = threadIdx.x;
    const int a0 = blockIdx.x * 64;

    #pragma unroll 4
    for (int i = 0; i < 128; ++i) sW2[i * 256 + t] = W2[i * 256 + t];
    #pragma unroll
    for (int i = 0; i < 8; ++i)   sW3[i * 256 + t] = W3[i * 256 + t];
    if (t < 128) sb2[t] = b2[t];
    if (t < 16)  sb3[t] = b3[t];
    if (t < 64) {
        int d = 0;
        #pragma unroll
        for (int p = 0; p < KSPL; ++p) d += g_degp[p][a0 + t];
        sInv[t] = 1.0f / (127.0f * (float)max(d, 1));
    }
    __syncthreads();
    #pragma unroll 4
    for (int i = 0; i < 32; ++i) {
        int idx = i * 256 + t;             // 8192 (agent,col) pairs
        int a = idx >> 7, k = idx & 127;
        sC[a * 257 + k] = g_h[(size_t)(a0 + a) * HID + k];
        int s = 0;
        #pragma unroll
        for (int p = 0; p < KSPL; ++p) s += g_msgp[p][(size_t)(a0 + a) * HID + k];
        sC[a * 257 + 128 + k] = (float)s * sInv[a];
    }
    __syncthreads();

    const int ar = t >> 4;    // agents ar*4 .. ar*4+3
    const int cc = t & 15;    // cols cc*8 .. cc*8+7
    float acc[4][8];
    #pragma unroll
    for (int j = 0; j < 4; ++j)
        #pragma unroll
        for (int i = 0; i < 8; ++i) acc[j][i] = 0.f;

    #pragma unroll 2
    for (int k = 0; k < 2 * HID; ++k) {
        float4 w0 = *reinterpret_cast<const float4*>(&sW2[k * 128 + cc * 8]);
        float4 w1 = *reinterpret_cast<const float4*>(&sW2[k * 128 + cc * 8 + 4]);
        #pragma unroll
        for (int j = 0; j < 4; ++j) {
            float cv = sC[(ar * 4 + j) * 257 + k];
            acc[j][0] = fmaf(cv, w0.x, acc[j][0]);
            acc[j][1] = fmaf(cv, w0.y, acc[j][1]);
            acc[j][2] = fmaf(cv, w0.z, acc[j][2]);
            acc[j][3] = fmaf(cv, w0.w, acc[j][3]);
            acc[j][4] = fmaf(cv, w1.x, acc[j][4]);
            acc[j][5] = fmaf(cv, w1.y, acc[j][5]);
            acc[j][6] = fmaf(cv, w1.z, acc[j][6]);
            acc[j][7] = fmaf(cv, w1.w, acc[j][7]);
        }
    }
    __syncthreads();                      // all comb reads done; reuse sC as hid
    float* sH = sC;                       // [64][129]
    #pragma unroll
    for (int j = 0; j < 4; ++j) {
        int a = ar * 4 + j;
        #pragma unroll
        for (int i = 0; i < 8; ++i) {
            int ccol = cc * 8 + i;
            sH[a * 129 + ccol] = tanhf(acc[j][i] + sb2[ccol]);
        }
    }
    __syncthreads();

    const int a  = t >> 2;   // 0..63
    const int cq = t & 3;    // col quad
    float4 lg; lg.x = 0.f; lg.y = 0.f; lg.z = 0.f; lg.w = 0.f;
    #pragma unroll 8
    for (int k = 0; k < HID; ++k) {
        float hv  = sH[a * 129 + k];
        float4 w3 = *reinterpret_cast<const float4*>(&sW3[k * 16 + cq * 4]);
        lg.x = fmaf(hv, w3.x, lg.x);
        lg.y = fmaf(hv, w3.y, lg.y);
        lg.z = fmaf(hv, w3.z, lg.z);
        lg.w = fmaf(hv, w3.w, lg.w);
    }
    lg.x += sb3[cq * 4 + 0];
    lg.y += sb3[cq * 4 + 1];
    lg.z += sb3[cq * 4 + 2];
    lg.w += sb3[cq * 4 + 3];
    *reinterpret_cast<float4*>(&out[(size_t)(a0 + a) * ACTD + cq * 4]) = lg;
}

// ---------------------------------------------------------------------------
extern "C" void kernel_launch(void* const* d_in, const int* in_sizes, int n_in,
                              void* d_out, int out_size) {
    const float* obs = (const float*)d_in[0];
    const int*   adj = (const int*)  d_in[1];
    const float* W1  = (const float*)d_in[2];
    const float* b1  = (const float*)d_in[3];
    const float* W2  = (const float*)d_in[4];
    const float* b2  = (const float*)d_in[5];
    const float* W3  = (const float*)d_in[6];
    const float* b3  = (const float*)d_in[7];
    float* out = (float*)d_out;

    cudaFuncSetAttribute(k2_msg,   cudaFuncAttributeMaxDynamicSharedMemorySize, K2_SMEM);
    cudaFuncSetAttribute(k3_actor, cudaFuncAttributeMaxDynamicSharedMemorySize, K3_SMEM);

    k1_encoder<<<NAG / 8, 256>>>(obs, W1, b1);
    k2_msg    <<<128 * KSPL, 256, K2_SMEM>>>(adj);
    k3_actor  <<<NAG / 64, 256, K3_SMEM>>>(out, W2, b2, W3, b3);
}